// round 9
// baseline (speedup 1.0000x reference)
#include <cuda_runtime.h>
#include <cuda_bf16.h>
#include <cstdint>

#define BDIM 2
#define C 256
#define H 96
#define W 96
#define HW (H*W)          // 9216
#define MPIX (BDIM*HW)    // 18432
#define OC 256
#define NTAP 9
#define KQ (NTAP*C)       // 2304
#define KQ2 (2*KQ)        // 4608 (a|b rows, c|d rows)
#define HP 98

// quantization scales: x ~= (a + b/256)/16, w ~= (c + d/256)/1024
#define SX 16.0f
#define SW 1024.0f

// -------- scratch (static device globals; no allocations) --------
__device__ __align__(128) int8_t g_Xq[(size_t)MPIX * KQ2];  // [m][a(2304)|b(2304)] 85MB
__device__ __align__(128) int8_t g_Wq[(size_t)OC * KQ2];    // [o][c(2304)|d(2304)] 1.2MB
__device__ __align__(128) float g_xT[(size_t)MPIX * C];     // NHWC transpose of x (19MB)
__device__ unsigned int g_qpack[NTAP * MPIX];
__device__ float4       g_w4[NTAP * MPIX];

// ---------------- PTX helpers (base ISA only) ----------------
__device__ __forceinline__ uint32_t smem_u32(const void* p) {
    uint32_t a;
    asm("{ .reg .u64 t; cvta.to.shared.u64 t, %1; cvt.u32.u64 %0, t; }" : "=r"(a) : "l"(p));
    return a;
}
__device__ __forceinline__ void cp16(uint32_t s, const void* g) {
    asm volatile("cp.async.cg.shared.global [%0], [%1], 16;" :: "r"(s), "l"(g));
}
__device__ __forceinline__ void cp_commit() {
    asm volatile("cp.async.commit_group;" ::: "memory");
}
template <int N> __device__ __forceinline__ void cp_wait() {
    asm volatile("cp.async.wait_group %0;" :: "n"(N) : "memory");
}
__device__ __forceinline__ uint32_t lds32(uint32_t a) {
    uint32_t v;
    asm("ld.shared.b32 %0, [%1];" : "=r"(v) : "r"(a));
    return v;
}
__device__ __forceinline__ void mma_s8(int* d, const uint32_t* a, const uint32_t* b) {
    asm volatile("mma.sync.aligned.m16n8k32.row.col.s32.s8.s8.s32 "
        "{%0,%1,%2,%3}, {%4,%5,%6,%7}, {%8,%9}, {%0,%1,%2,%3};"
        : "+r"(d[0]), "+r"(d[1]), "+r"(d[2]), "+r"(d[3])
        : "r"(a[0]), "r"(a[1]), "r"(a[2]), "r"(a[3]), "r"(b[0]), "r"(b[1]));
}
__device__ __forceinline__ unsigned long long fma2(
    unsigned long long a, unsigned long long b, unsigned long long c)
{
    unsigned long long d;
    asm("fma.rn.f32x2 %0, %1, %2, %3;" : "=l"(d) : "l"(a), "l"(b), "l"(c));
    return d;
}
__device__ __forceinline__ unsigned long long pack2(float v) {
    unsigned long long d;
    asm("mov.b64 %0, {%1, %1};" : "=l"(d) : "f"(v));
    return d;
}
__device__ __forceinline__ uint32_t swz(uint32_t off) { return off ^ ((off >> 3) & 0x70); }

__device__ __forceinline__ int q8(float v) {
    int i = __float2int_rn(v);
    return min(max(i, -127), 127);
}

// ================= Kernel 0: weight int8 two-level quant =================
// w ~= (c + d/256) / 1024
__global__ void __launch_bounds__(256) wq_kernel(const float* __restrict__ wc)
{
    int o = blockIdx.x;
    int c = threadIdx.x;
#pragma unroll
    for (int k = 0; k < 9; k++) {
        float w = __ldg(&wc[((size_t)o*C + c)*9 + k]);
        float wq = w * SW;
        int c8 = q8(wq);
        int d8 = q8((wq - (float)c8) * 256.0f);
        g_Wq[(size_t)o * KQ2 + k*C + c]       = (int8_t)c8;
        g_Wq[(size_t)o * KQ2 + KQ + k*C + c]  = (int8_t)d8;
    }
}

// ================= Kernel 0b: NCHW -> NHWC transpose =================
__global__ void __launch_bounds__(256) tr_kernel(const float* __restrict__ x)
{
    __shared__ float tile[32][33];
    const int b   = blockIdx.z;
    const int c0  = blockIdx.y * 32;
    const int hw0 = blockIdx.x * 32;
    const int tx = threadIdx.x & 31;
    const int ty = threadIdx.x >> 5;
#pragma unroll
    for (int r = 0; r < 4; r++) {
        int c = c0 + ty + r * 8;
        tile[ty + r * 8][tx] = x[(size_t)(b * C + c) * HW + hw0 + tx];
    }
    __syncthreads();
#pragma unroll
    for (int r = 0; r < 4; r++) {
        int hw = hw0 + ty + r * 8;
        g_xT[(size_t)(b * HW + hw) * C + c0 + tx] = tile[tx][ty + r * 8];
    }
}

// ================= Kernel 1: offset conv (f32x2, oc-pair accum) =================
__global__ void __launch_bounds__(256) offset_kernel(
    const float* __restrict__ x,  const float* __restrict__ w_p,
    const float* __restrict__ b_p, const float* __restrict__ w_ad,
    const float* __restrict__ b_ad)
{
    const int tid = threadIdx.x;
    const int tx  = tid & 63;
    const int ty  = tid >> 6;
    const int mA  = blockIdx.x * 128 + tx;
    const int mB  = mA + 64;

    __shared__ float wbuf[32][200];
    __shared__ float red[4][21][64];

    const int bA = mA / HW, hwA = mA % HW, hA = hwA / W, wA = hwA % W;
    const int bB = mB / HW, hwB = mB % HW, hB = hwB / W, wB = hwB % W;

    unsigned long long accA[11], accB[11];
#pragma unroll
    for (int i = 0; i < 11; i++) { accA[i] = 0ull; accB[i] = 0ull; }

    if (tid < 32) {
#pragma unroll
        for (int t = 0; t < 9; t++) wbuf[tid][t*22 + 21] = 0.f;
    }

    const float* xA = x + (size_t)bA * C * HW;
    const float* xB = x + (size_t)bB * C * HW;

#pragma unroll 1
    for (int ch = 0; ch < 8; ch++) {
        __syncthreads();
        for (int idx = tid; idx < 32 * 189; idx += 256) {
            int row = idx / 189, e = idx % 189;
            int oc = e / 9, t = e % 9;
            int c = (row >> 3) * 64 + ch * 8 + (row & 7);
            float wv = (oc < 18) ? __ldg(&w_p[((size_t)oc*C + c)*9 + t])
                                 : __ldg(&w_ad[((size_t)(oc-18)*C + c)*9 + t]);
            wbuf[row][t*22 + oc] = wv;
        }
        __syncthreads();
#pragma unroll 1
        for (int cc = 0; cc < 8; cc++) {
            const int c = ty * 64 + ch * 8 + cc;
            const float* plA = xA + (size_t)c * HW;
            const float* plB = xB + (size_t)c * HW;
            float vA[9], vB[9];
#pragma unroll
            for (int t = 0; t < 9; t++) {
                int dh = t / 3 - 1, dw = t % 3 - 1;
                int h1 = hA + dh, w1 = wA + dw;
                vA[t] = (h1 >= 0 && h1 < H && w1 >= 0 && w1 < W) ? __ldg(&plA[h1*W + w1]) : 0.f;
                int h2 = hB + dh, w2 = wB + dw;
                vB[t] = (h2 >= 0 && h2 < H && w2 >= 0 && w2 < W) ? __ldg(&plB[h2*W + w2]) : 0.f;
            }
            const float* wr = &wbuf[ty * 8 + cc][0];
#pragma unroll
            for (int t = 0; t < 9; t++) {
                unsigned long long aA = pack2(vA[t]);
                unsigned long long aB = pack2(vB[t]);
#pragma unroll
                for (int o2 = 0; o2 < 11; o2++) {
                    unsigned long long wpair =
                        *(const unsigned long long*)&wr[t*22 + o2*2];
                    accA[o2] = fma2(wpair, aA, accA[o2]);
                    accB[o2] = fma2(wpair, aB, accB[o2]);
                }
            }
        }
    }

#pragma unroll 1
    for (int p = 0; p < 2; p++) {
        __syncthreads();
#pragma unroll
        for (int o2 = 0; o2 < 11; o2++) {
            unsigned long long v = p ? accB[o2] : accA[o2];
            float lo = __uint_as_float((unsigned)(v & 0xffffffffull));
            float hi = __uint_as_float((unsigned)(v >> 32));
            red[ty][o2*2][tx] = lo;
            if (o2 < 10) red[ty][o2*2+1][tx] = hi;
        }
        __syncthreads();
        if (ty == 0) {
            const int m = (p == 0) ? mA : mB;
            const int h = (p == 0) ? hA : hB;
            const int w = (p == 0) ? wA : wB;
            float a[21];
#pragma unroll
            for (int oc = 0; oc < 21; oc++)
                a[oc] = red[0][oc][tx] + red[1][oc][tx] + red[2][oc][tx] + red[3][oc][tx];
#pragma unroll
            for (int k = 0; k < 9; k++) {
                float pnx = (float)(k / 3) - 1.f;
                float pny = (float)(k % 3) - 1.f;
                float z   = a[18 + (k % 3)] + __ldg(&b_ad[k % 3]);
                float sig = 1.f / (1.f + expf(-z));
                float ad  = 2.f * (1.f - sig);
                float px = (float)(h + 1) + pnx + a[k]     + __ldg(&b_p[k])     + ad * pnx;
                float py = (float)(w + 1) + pny + a[9 + k] + __ldg(&b_p[9 + k]) + ad * pny;
                float fx = floorf(px), fy = floorf(py);
                int iltx = (int)fx, ilty = (int)fy;
                int ltx = min(max(iltx,     0), HP - 1), lty = min(max(ilty,     0), HP - 1);
                int rbx = min(max(iltx + 1, 0), HP - 1), rby = min(max(ilty + 1, 0), HP - 1);
                bool mx = (px < 1.f) || (px > (float)(HP - 2));
                bool my = (py < 1.f) || (py > (float)(HP - 2));
                if (mx) px = fx;
                if (my) py = fy;
                px = fminf(fmaxf(px, 0.f), (float)(HP - 1));
                py = fminf(fmaxf(py, 0.f), (float)(HP - 1));
                float dxl = 1.f + ((float)ltx - px);
                float dyl = 1.f + ((float)lty - py);
                float dxr = 1.f - ((float)rbx - px);
                float dyr = 1.f - ((float)rby - py);
                g_qpack[k*MPIX + m] = (unsigned)ltx | ((unsigned)lty << 8)
                                    | ((unsigned)rbx << 16) | ((unsigned)rby << 24);
                g_w4[k*MPIX + m] = make_float4(dxl*dyl, dxr*dyr, dxl*dyr, dxr*dyl);
            }
        }
    }
}

// ================= Kernel 2: bilinear gather (NHWC) -> int8 two-level X =================
__global__ void __launch_bounds__(256) sample_kernel()
{
    const int tid  = threadIdx.x;
    const int wid  = tid >> 5, lane = tid & 31;
    const int pid  = blockIdx.x * 8 + wid;
    const int k    = pid / MPIX;
    const int m    = pid % MPIX;

    const unsigned qp = g_qpack[k*MPIX + m];
    const float4 g = g_w4[k*MPIX + m];
    const int ltx = qp & 255, lty = (qp >> 8) & 255, rbx = (qp >> 16) & 255, rby = (qp >> 24) & 255;
    const bool ax  = (ltx >= 1) && (ltx <= 96);
    const bool axr = (rbx >= 1) && (rbx <= 96);
    const bool ay  = (lty >= 1) && (lty <= 96);
    const bool ayr = (rby >= 1) && (rby <= 96);
    const float glt = (ax  && ay ) ? g.x : 0.f;
    const float grb = (axr && ayr) ? g.y : 0.f;
    const float glb = (ax  && ayr) ? g.z : 0.f;
    const float grt = (axr && ay ) ? g.w : 0.f;
    const int b = m / HW;
    const size_t base = (size_t)b * HW * C;
    const size_t oLT = (ax  && ay ) ? base + (size_t)((ltx-1)*W + (lty-1)) * C : base;
    const size_t oRB = (axr && ayr) ? base + (size_t)((rbx-1)*W + (rby-1)) * C : base;
    const size_t oLB = (ax  && ayr) ? base + (size_t)((ltx-1)*W + (rby-1)) * C : base;
    const size_t oRT = (axr && ay ) ? base + (size_t)((rbx-1)*W + (lty-1)) * C : base;

    const int c0 = lane * 8;
    float4 vLT0 = *(const float4*)&g_xT[oLT + c0];
    float4 vLT1 = *(const float4*)&g_xT[oLT + c0 + 4];
    float4 vRB0 = *(const float4*)&g_xT[oRB + c0];
    float4 vRB1 = *(const float4*)&g_xT[oRB + c0 + 4];
    float4 vLB0 = *(const float4*)&g_xT[oLB + c0];
    float4 vLB1 = *(const float4*)&g_xT[oLB + c0 + 4];
    float4 vRT0 = *(const float4*)&g_xT[oRT + c0];
    float4 vRT1 = *(const float4*)&g_xT[oRT + c0 + 4];

    float v[8];
    v[0] = glt*vLT0.x + grb*vRB0.x + glb*vLB0.x + grt*vRT0.x;
    v[1] = glt*vLT0.y + grb*vRB0.y + glb*vLB0.y + grt*vRT0.y;
    v[2] = glt*vLT0.z + grb*vRB0.z + glb*vLB0.z + grt*vRT0.z;
    v[3] = glt*vLT0.w + grb*vRB0.w + glb*vLB0.w + grt*vRT0.w;
    v[4] = glt*vLT1.x + grb*vRB1.x + glb*vLB1.x + grt*vRT1.x;
    v[5] = glt*vLT1.y + grb*vRB1.y + glb*vLB1.y + grt*vRT1.y;
    v[6] = glt*vLT1.z + grb*vRB1.z + glb*vLB1.z + grt*vRT1.z;
    v[7] = glt*vLT1.w + grb*vRB1.w + glb*vLB1.w + grt*vRT1.w;

    // x ~= (a + b/256) / 16
    uint32_t aw[2] = {0u, 0u}, bw[2] = {0u, 0u};
#pragma unroll
    for (int j = 0; j < 8; j++) {
        float q = v[j] * SX;
        int ai = q8(q);
        int bi = q8((q - (float)ai) * 256.0f);
        aw[j >> 2] |= ((uint32_t)(ai & 255)) << ((j & 3) * 8);
        bw[j >> 2] |= ((uint32_t)(bi & 255)) << ((j & 3) * 8);
    }
    char* dst = (char*)g_Xq + (size_t)m * KQ2 + k * C + lane * 8;
    *(uint2*)(dst)      = make_uint2(aw[0], aw[1]);
    *(uint2*)(dst + KQ) = make_uint2(bw[0], bw[1]);
}

// ================= Kernel 3: int8 IMMA double GEMM =================
// acc1 = a.cT (K=2304); acc2 = a.dT + b.cT
// out = acc1/(SX*SW) + acc2/(SX*SW*256)
#define QBK 128               // k-chunk bytes
#define QNKIT (KQ / QBK)      // 18
#define QNST 3
#define T_A 16384             // 128 x 128 bytes
#define QSTG (4 * T_A)        // a,b,c,d tiles = 64KB
#define QSMEM (QNST * QSTG)   // 192KB

__device__ __forceinline__ void load_stage_q(uint32_t base, const char* Ag, const char* Bg,
                                             int t, int tid)
{
    const size_t koff = (size_t)t * QBK;
#pragma unroll
    for (int j = 0; j < 16; j++) {
        int chunk = tid + j * 256;          // 0..4095
        int s = chunk >> 10;                // 0:a 1:b 2:c 3:d
        int within = chunk & 1023;
        int r = within >> 3, cc = within & 7;
        uint32_t dst = base + s * T_A + swz((uint32_t)(r * 128 + cc * 16));
        const char* src = (s < 2 ? Ag : Bg) + (size_t)r * KQ2 + (s & 1) * KQ + koff + cc * 16;
        cp16(dst, src);
    }
    cp_commit();
}

__global__ void __launch_bounds__(256, 1) mma_kernel(float* __restrict__ out)
{
    extern __shared__ char smem[];
    const uint32_t sb = smem_u32(smem);
    const int tid = threadIdx.x;
    const int wid = tid >> 5, lane = tid & 31;
    const int m0 = blockIdx.x * 128;
    const int o0 = blockIdx.y * 128;

    const char* Ag = (const char*)g_Xq + (size_t)m0 * KQ2;
    const char* Bg = (const char*)g_Wq + (size_t)o0 * KQ2;

    const int wm = (wid & 3) * 32;    // 4 m-groups of 32
    const int wn = (wid >> 2) * 64;   // 2 n-groups of 64

    int acc1[2][8][4], acc2[2][8][4];
#pragma unroll
    for (int mi = 0; mi < 2; mi++)
#pragma unroll
        for (int ni = 0; ni < 8; ni++)
#pragma unroll
            for (int r = 0; r < 4; r++) { acc1[mi][ni][r] = 0; acc2[mi][ni][r] = 0; }

    const int lrow = lane >> 2;           // fragment row within 8
    const int lkb  = (lane & 3) * 4;      // fragment k-byte

    load_stage_q(sb,        Ag, Bg, 0, tid);
    load_stage_q(sb + QSTG, Ag, Bg, 1, tid);

#pragma unroll 1
    for (int t = 0; t < QNKIT; t++) {
        if (t + 1 < QNKIT) cp_wait<1>(); else cp_wait<0>();
        __syncthreads();
        const uint32_t Aa = sb + (t % QNST) * QSTG;
        const uint32_t Ab = Aa + T_A;
        const uint32_t Bc = Aa + 2 * T_A;
        const uint32_t Bd = Aa + 3 * T_A;
#pragma unroll
        for (int ks = 0; ks < 4; ks++) {
            const int kb = ks * 32 + lkb;
            uint32_t fa[2][4], fb[2][4], fc[8][2], fd[8][2];
#pragma unroll
            for (int mi = 0; mi < 2; mi++) {
                uint32_t off = (uint32_t)((wm + mi * 16 + lrow) * 128 + kb);
                fa[mi][0] = lds32(Aa + swz(off));
                fa[mi][1] = lds32(Aa + swz(off + 1024));
                fa[mi][2] = lds32(Aa + swz(off + 16));
                fa[mi][3] = lds32(Aa + swz(off + 1040));
                fb[mi][0] = lds32(Ab + swz(off));
                fb[mi][1] = lds32(Ab + swz(off + 1024));
                fb[mi][2] = lds32(Ab + swz(off + 16));
                fb[mi][3] = lds32(Ab + swz(off + 1040));
            }
#pragma unroll
            for (int ni = 0; ni < 8; ni++) {
                uint32_t off = (uint32_t)((wn + ni * 8 + lrow) * 128 + kb);
                fc[ni][0] = lds32(Bc + swz(off));
                fc[ni][1] = lds32(Bc + swz(off + 16));
                fd[ni][0] = lds32(Bd + swz(off));
                fd[ni][1] = lds32(Bd + swz(off + 16));
            }
#pragma unroll
            for (int mi = 0; mi < 2; mi++)
#pragma unroll
                for (int ni = 0; ni < 8; ni++) {
                    mma_s8(acc1[mi][ni], fa[mi], fc[ni]);
                    mma_s8(acc2[mi][ni], fa[mi], fd[ni]);
                    mma_s8(acc2[mi][ni], fb[mi], fc[ni]);
                }
        }
        int u = t + 2;
        if (u < QNKIT) load_stage_q(sb + (u % QNST) * QSTG, Ag, Bg, u, tid);
    }

    // ---- epilogue: combine scales, smem transpose to [o][m], coalesced stores ----
    const float S1 = 1.0f / (SX * SW);            // 1/16384
    const float S2 = 1.0f / (SX * SW * 256.0f);   // 1/4194304
    __syncthreads();
    float* eb = (float*)smem;                 // 128 x 132 floats = 67.6KB
    const int er = lane >> 2;
    const int ec = (lane & 3) * 2;
#pragma unroll
    for (int mi = 0; mi < 2; mi++) {
#pragma unroll
        for (int ni = 0; ni < 8; ni++) {
            int m = wm + mi * 16 + er;
            int o = wn + ni * 8 + ec;
            float f0 = (float)acc1[mi][ni][0] * S1 + (float)acc2[mi][ni][0] * S2;
            float f1 = (float)acc1[mi][ni][1] * S1 + (float)acc2[mi][ni][1] * S2;
            float f2 = (float)acc1[mi][ni][2] * S1 + (float)acc2[mi][ni][2] * S2;
            float f3 = (float)acc1[mi][ni][3] * S1 + (float)acc2[mi][ni][3] * S2;
            eb[(o    ) * 132 + m    ] = f0;
            eb[(o + 1) * 132 + m    ] = f1;
            eb[(o    ) * 132 + m + 8] = f2;
            eb[(o + 1) * 132 + m + 8] = f3;
        }
    }
    __syncthreads();
    const int b   = m0 / HW;
    const int hw0 = m0 % HW;
#pragma unroll
    for (int i = 0; i < 16; i++) {
        int idx = tid + i * 256;
        int r = idx >> 5, c4 = (idx & 31) * 4;
        float4 v = *(const float4*)&eb[r * 132 + c4];
        *(float4*)&out[(size_t)(b * OC + o0 + r) * HW + hw0 + c4] = v;
    }
}

// ================= launch =================
extern "C" void kernel_launch(void* const* d_in, const int* in_sizes, int n_in,
                              void* d_out, int out_size)
{
    const float* x      = (const float*)d_in[0];
    const float* w_p    = (const float*)d_in[1];
    const float* b_p    = (const float*)d_in[2];
    const float* w_ad   = (const float*)d_in[3];
    const float* b_ad   = (const float*)d_in[4];
    const float* w_conv = (const float*)d_in[5];
    float* out = (float*)d_out;

    cudaFuncSetAttribute(mma_kernel, cudaFuncAttributeMaxDynamicSharedMemorySize, QSMEM);

    wq_kernel<<<OC, 256>>>(w_conv);
    tr_kernel<<<dim3(HW / 32, C / 32, BDIM), 256>>>(x);
    offset_kernel<<<MPIX / 128, 256>>>(x, w_p, b_p, w_ad, b_ad);
    sample_kernel<<<MPIX * NTAP / 8, 256>>>();
    mma_kernel<<<dim3(MPIX / 128, OC / 128), 256, QSMEM>>>(out);
}

// round 10
// speedup vs baseline: 1.8671x; 1.8671x over previous
#include <cuda_runtime.h>
#include <cuda_bf16.h>
#include <cstdint>

#define BDIM 2
#define C 256
#define H 96
#define W 96
#define HW (H*W)          // 9216
#define MPIX (BDIM*HW)    // 18432
#define OC 256
#define NTAP 9
#define KQ (NTAP*C)       // 2304 logical K
#define KD2 (2*KQ)        // 4608 (hi | lo)
#define HP 98

// -------- scratch (static device globals; no allocations) --------
__device__ __align__(128) __nv_bfloat16 g_Wb2[(size_t)OC * KD2]; // [o][hi(2304)|lo(2304)] 2.4MB
__device__ __align__(128) float g_xT[(size_t)MPIX * C];          // NHWC x (19MB, L2-resident)
__device__ unsigned int g_qpack[NTAP * MPIX];
__device__ float4       g_w4[NTAP * MPIX];

// ---------------- PTX helpers (base ISA only) ----------------
__device__ __forceinline__ uint32_t smem_u32(const void* p) {
    uint32_t a;
    asm("{ .reg .u64 t; cvta.to.shared.u64 t, %1; cvt.u32.u64 %0, t; }" : "=r"(a) : "l"(p));
    return a;
}
__device__ __forceinline__ void cp16(uint32_t s, const void* g) {
    asm volatile("cp.async.cg.shared.global [%0], [%1], 16;" :: "r"(s), "l"(g));
}
__device__ __forceinline__ void cp_commit() {
    asm volatile("cp.async.commit_group;" ::: "memory");
}
template <int N> __device__ __forceinline__ void cp_wait() {
    asm volatile("cp.async.wait_group %0;" :: "n"(N) : "memory");
}
__device__ __forceinline__ void sts32(uint32_t a, uint32_t v) {
    asm volatile("st.shared.b32 [%0], %1;" :: "r"(a), "r"(v) : "memory");
}
__device__ __forceinline__ void ldsm_x4(uint32_t* r, uint32_t addr) {
    asm volatile("ldmatrix.sync.aligned.m8n8.x4.shared.b16 {%0,%1,%2,%3}, [%4];"
        : "=r"(r[0]), "=r"(r[1]), "=r"(r[2]), "=r"(r[3]) : "r"(addr));
}
__device__ __forceinline__ void mma16816(float* d, const uint32_t* a, const uint32_t* b) {
    asm volatile("mma.sync.aligned.m16n8k16.row.col.f32.bf16.bf16.f32 "
        "{%0,%1,%2,%3}, {%4,%5,%6,%7}, {%8,%9}, {%0,%1,%2,%3};"
        : "+f"(d[0]), "+f"(d[1]), "+f"(d[2]), "+f"(d[3])
        : "r"(a[0]), "r"(a[1]), "r"(a[2]), "r"(a[3]), "r"(b[0]), "r"(b[1]));
}
__device__ __forceinline__ unsigned long long fma2(
    unsigned long long a, unsigned long long b, unsigned long long c)
{
    unsigned long long d;
    asm("fma.rn.f32x2 %0, %1, %2, %3;" : "=l"(d) : "l"(a), "l"(b), "l"(c));
    return d;
}
__device__ __forceinline__ unsigned long long pack2(float v) {
    unsigned long long d;
    asm("mov.b64 %0, {%1, %1};" : "=l"(d) : "f"(v));
    return d;
}
__device__ __forceinline__ uint32_t swz(uint32_t off) { return off ^ ((off >> 3) & 0x70); }

// ================= Kernel 0: weight bf16 hi/lo split =================
__global__ void __launch_bounds__(256) wq_kernel(const float* __restrict__ wc)
{
    int o = blockIdx.x;
    int c = threadIdx.x;
#pragma unroll
    for (int k = 0; k < 9; k++) {
        float w = __ldg(&wc[((size_t)o*C + c)*9 + k]);
        __nv_bfloat16 hi = __float2bfloat16(w);
        __nv_bfloat16 lo = __float2bfloat16(w - __bfloat162float(hi));
        g_Wb2[(size_t)o * KD2 + k*C + c]      = hi;
        g_Wb2[(size_t)o * KD2 + KQ + k*C + c] = lo;
    }
}

// ================= Kernel 0b: NCHW -> NHWC transpose =================
__global__ void __launch_bounds__(256) tr_kernel(const float* __restrict__ x)
{
    __shared__ float tile[32][33];
    const int b   = blockIdx.z;
    const int c0  = blockIdx.y * 32;
    const int hw0 = blockIdx.x * 32;
    const int tx = threadIdx.x & 31;
    const int ty = threadIdx.x >> 5;
#pragma unroll
    for (int r = 0; r < 4; r++) {
        int c = c0 + ty + r * 8;
        tile[ty + r * 8][tx] = x[(size_t)(b * C + c) * HW + hw0 + tx];
    }
    __syncthreads();
#pragma unroll
    for (int r = 0; r < 4; r++) {
        int hw = hw0 + ty + r * 8;
        g_xT[(size_t)(b * HW + hw) * C + c0 + tx] = tile[tx][ty + r * 8];
    }
}

// ================= Kernel 1: offset conv (f32x2, oc-pair accum) =================
__global__ void __launch_bounds__(256) offset_kernel(
    const float* __restrict__ x,  const float* __restrict__ w_p,
    const float* __restrict__ b_p, const float* __restrict__ w_ad,
    const float* __restrict__ b_ad)
{
    const int tid = threadIdx.x;
    const int tx  = tid & 63;
    const int ty  = tid >> 6;
    const int mA  = blockIdx.x * 128 + tx;
    const int mB  = mA + 64;

    __shared__ float wbuf[32][200];
    __shared__ float red[4][21][64];

    const int bA = mA / HW, hwA = mA % HW, hA = hwA / W, wA = hwA % W;
    const int bB = mB / HW, hwB = mB % HW, hB = hwB / W, wB = hwB % W;

    unsigned long long accA[11], accB[11];
#pragma unroll
    for (int i = 0; i < 11; i++) { accA[i] = 0ull; accB[i] = 0ull; }

    if (tid < 32) {
#pragma unroll
        for (int t = 0; t < 9; t++) wbuf[tid][t*22 + 21] = 0.f;
    }

    const float* xA = x + (size_t)bA * C * HW;
    const float* xB = x + (size_t)bB * C * HW;

#pragma unroll 1
    for (int ch = 0; ch < 8; ch++) {
        __syncthreads();
        for (int idx = tid; idx < 32 * 189; idx += 256) {
            int row = idx / 189, e = idx % 189;
            int oc = e / 9, t = e % 9;
            int c = (row >> 3) * 64 + ch * 8 + (row & 7);
            float wv = (oc < 18) ? __ldg(&w_p[((size_t)oc*C + c)*9 + t])
                                 : __ldg(&w_ad[((size_t)(oc-18)*C + c)*9 + t]);
            wbuf[row][t*22 + oc] = wv;
        }
        __syncthreads();
#pragma unroll 1
        for (int cc = 0; cc < 8; cc++) {
            const int c = ty * 64 + ch * 8 + cc;
            const float* plA = xA + (size_t)c * HW;
            const float* plB = xB + (size_t)c * HW;
            float vA[9], vB[9];
#pragma unroll
            for (int t = 0; t < 9; t++) {
                int dh = t / 3 - 1, dw = t % 3 - 1;
                int h1 = hA + dh, w1 = wA + dw;
                vA[t] = (h1 >= 0 && h1 < H && w1 >= 0 && w1 < W) ? __ldg(&plA[h1*W + w1]) : 0.f;
                int h2 = hB + dh, w2 = wB + dw;
                vB[t] = (h2 >= 0 && h2 < H && w2 >= 0 && w2 < W) ? __ldg(&plB[h2*W + w2]) : 0.f;
            }
            const float* wr = &wbuf[ty * 8 + cc][0];
#pragma unroll
            for (int t = 0; t < 9; t++) {
                unsigned long long aA = pack2(vA[t]);
                unsigned long long aB = pack2(vB[t]);
#pragma unroll
                for (int o2 = 0; o2 < 11; o2++) {
                    unsigned long long wpair =
                        *(const unsigned long long*)&wr[t*22 + o2*2];
                    accA[o2] = fma2(wpair, aA, accA[o2]);
                    accB[o2] = fma2(wpair, aB, accB[o2]);
                }
            }
        }
    }

#pragma unroll 1
    for (int p = 0; p < 2; p++) {
        __syncthreads();
#pragma unroll
        for (int o2 = 0; o2 < 11; o2++) {
            unsigned long long v = p ? accB[o2] : accA[o2];
            float lo = __uint_as_float((unsigned)(v & 0xffffffffull));
            float hi = __uint_as_float((unsigned)(v >> 32));
            red[ty][o2*2][tx] = lo;
            if (o2 < 10) red[ty][o2*2+1][tx] = hi;
        }
        __syncthreads();
        if (ty == 0) {
            const int m = (p == 0) ? mA : mB;
            const int h = (p == 0) ? hA : hB;
            const int w = (p == 0) ? wA : wB;
            float a[21];
#pragma unroll
            for (int oc = 0; oc < 21; oc++)
                a[oc] = red[0][oc][tx] + red[1][oc][tx] + red[2][oc][tx] + red[3][oc][tx];
#pragma unroll
            for (int k = 0; k < 9; k++) {
                float pnx = (float)(k / 3) - 1.f;
                float pny = (float)(k % 3) - 1.f;
                float z   = a[18 + (k % 3)] + __ldg(&b_ad[k % 3]);
                float sig = 1.f / (1.f + expf(-z));
                float ad  = 2.f * (1.f - sig);
                float px = (float)(h + 1) + pnx + a[k]     + __ldg(&b_p[k])     + ad * pnx;
                float py = (float)(w + 1) + pny + a[9 + k] + __ldg(&b_p[9 + k]) + ad * pny;
                float fx = floorf(px), fy = floorf(py);
                int iltx = (int)fx, ilty = (int)fy;
                int ltx = min(max(iltx,     0), HP - 1), lty = min(max(ilty,     0), HP - 1);
                int rbx = min(max(iltx + 1, 0), HP - 1), rby = min(max(ilty + 1, 0), HP - 1);
                bool mx = (px < 1.f) || (px > (float)(HP - 2));
                bool my = (py < 1.f) || (py > (float)(HP - 2));
                if (mx) px = fx;
                if (my) py = fy;
                px = fminf(fmaxf(px, 0.f), (float)(HP - 1));
                py = fminf(fmaxf(py, 0.f), (float)(HP - 1));
                float dxl = 1.f + ((float)ltx - px);
                float dyl = 1.f + ((float)lty - py);
                float dxr = 1.f - ((float)rbx - px);
                float dyr = 1.f - ((float)rby - py);
                g_qpack[k*MPIX + m] = (unsigned)ltx | ((unsigned)lty << 8)
                                    | ((unsigned)rbx << 16) | ((unsigned)rby << 24);
                g_w4[k*MPIX + m] = make_float4(dxl*dyl, dxr*dyr, dxl*dyr, dxr*dyl);
            }
        }
    }
}

// ================= Kernel 2: fused sample + HMMA GEMM =================
// CTA: 128 m x 256 o, 512 threads (16 warps, warp tile 32m x 64o), grid 144.
// K-chunks: 36 chunks of 64 columns; chunk t: tap = t>>2, channels (t&3)*64..+64.
// acc += Ahi.BhiT + Alo.BhiT + Ahi.BloT  (A fragments reused).
#define NCH 36
#define ST_AH 0
#define ST_AL 16384
#define ST_BH 32768
#define ST_BL 65536
#define STAGE 98304
#define FUSE_SMEM (2 * STAGE)    // 192KB

// B producer: cp.async both W parts for chunk t into stage buffer
__device__ __forceinline__ void produce_B(uint32_t stg, int t, int tid)
{
    const char* Wb = (const char*)g_Wb2;
#pragma unroll
    for (int j = 0; j < 8; j++) {
        int idx = tid + j * 512;            // 0..4095
        int part = idx >> 11;               // 0: hi, 1: lo
        int within = idx & 2047;
        int o = within >> 3, cc = within & 7;
        uint32_t dst = stg + ST_BH + part * 32768
                     + swz((uint32_t)(o * 128 + cc * 16));
        cp16(dst, Wb + (size_t)o * (KD2 * 2) + part * (KQ * 2) + t * 128 + cc * 16);
    }
}

// A producer: gather + bilinear + hi/lo split for chunk t into stage buffer
__device__ __forceinline__ void produce_A(uint32_t stg, int t, int m0, int wid, int lane)
{
    const int tap = t >> 2;
    const int c0  = (t & 3) * 64;
    const int cix = c0 + lane * 2;
#pragma unroll 2
    for (int r = 0; r < 8; r++) {
        const int m_l = wid * 8 + r;
        const int m = m0 + m_l;
        const unsigned qp = g_qpack[tap*MPIX + m];
        const float4 g = g_w4[tap*MPIX + m];
        const int ltx = qp & 255, lty = (qp >> 8) & 255;
        const int rbx = (qp >> 16) & 255, rby = (qp >> 24) & 255;
        const bool ax  = (ltx >= 1) && (ltx <= 96);
        const bool axr = (rbx >= 1) && (rbx <= 96);
        const bool ay  = (lty >= 1) && (lty <= 96);
        const bool ayr = (rby >= 1) && (rby <= 96);
        const float glt = (ax  && ay ) ? g.x : 0.f;
        const float grb = (axr && ayr) ? g.y : 0.f;
        const float glb = (ax  && ayr) ? g.z : 0.f;
        const float grt = (axr && ay ) ? g.w : 0.f;
        const unsigned base = (unsigned)(m / HW) * (HW * C);
        const unsigned oLT = (ax  && ay ) ? base + (unsigned)((ltx-1)*W + (lty-1)) * C : base;
        const unsigned oRB = (axr && ayr) ? base + (unsigned)((rbx-1)*W + (rby-1)) * C : base;
        const unsigned oLB = (ax  && ayr) ? base + (unsigned)((ltx-1)*W + (rby-1)) * C : base;
        const unsigned oRT = (axr && ay ) ? base + (unsigned)((rbx-1)*W + (lty-1)) * C : base;

        float2 eLT = *(const float2*)&g_xT[oLT + cix];
        float2 eRB = *(const float2*)&g_xT[oRB + cix];
        float2 eLB = *(const float2*)&g_xT[oLB + cix];
        float2 eRT = *(const float2*)&g_xT[oRT + cix];
        float v0 = glt*eLT.x + grb*eRB.x + glb*eLB.x + grt*eRT.x;
        float v1 = glt*eLT.y + grb*eRB.y + glb*eLB.y + grt*eRT.y;

        __nv_bfloat16 h0 = __float2bfloat16(v0);
        __nv_bfloat16 h1 = __float2bfloat16(v1);
        __nv_bfloat16 l0 = __float2bfloat16(v0 - __bfloat162float(h0));
        __nv_bfloat16 l1 = __float2bfloat16(v1 - __bfloat162float(h1));
        uint32_t hw_ = (uint32_t)*(unsigned short*)&h0 | ((uint32_t)*(unsigned short*)&h1 << 16);
        uint32_t lw_ = (uint32_t)*(unsigned short*)&l0 | ((uint32_t)*(unsigned short*)&l1 << 16);
        uint32_t offA = swz((uint32_t)(m_l * 128 + lane * 4));
        sts32(stg + ST_AH + offA, hw_);
        sts32(stg + ST_AL + offA, lw_);
    }
}

__global__ void __launch_bounds__(512, 1) mma_kernel(float* __restrict__ out)
{
    extern __shared__ char smem[];
    const uint32_t sb = smem_u32(smem);
    const int tid = threadIdx.x;
    const int wid = tid >> 5, lane = tid & 31;
    const int m0 = blockIdx.x * 128;

    const int wm = (wid >> 2) * 32;   // 4 m-groups of 32
    const int wn = (wid & 3) * 64;    // 4 n-groups of 64

    float acc[2][8][4];
#pragma unroll
    for (int mi = 0; mi < 2; mi++)
#pragma unroll
        for (int ni = 0; ni < 8; ni++)
#pragma unroll
            for (int r = 0; r < 4; r++) acc[mi][ni][r] = 0.f;

    const int a_row = wm + (lane & 15);
    const int a_cb  = (lane >> 4) * 16;
    const int b_row = wn + (lane & 7) + ((lane >> 4) << 3);
    const int b_cb  = ((lane >> 3) & 1) * 16;

    // prologue
    produce_B(sb, 0, tid);
    cp_commit();
    produce_A(sb, 0, m0, wid, lane);

#pragma unroll 1
    for (int t = 0; t < NCH; t++) {
        const uint32_t stg  = sb + (t & 1) * STAGE;
        const uint32_t stgN = sb + ((t + 1) & 1) * STAGE;
        __syncthreads();                       // everyone done with consume(t-1)
        if (t + 1 < NCH) produce_B(stgN, t + 1, tid);
        cp_commit();
        cp_wait<1>();                          // B(t) complete (this thread)
        __syncthreads();                       // B(t) + A(t) visible to all

        // ---- consume chunk t ----
        const uint32_t Ah = stg + ST_AH;
        const uint32_t Al = stg + ST_AL;
        const uint32_t Bh = stg + ST_BH;
        const uint32_t Bl = stg + ST_BL;
#pragma unroll
        for (int kk = 0; kk < 4; kk++) {
            const int kb = kk * 32;
            uint32_t ah[2][4], al[2][4], bf[4][4];
#pragma unroll
            for (int mi = 0; mi < 2; mi++) {
                uint32_t off = (uint32_t)((a_row + mi * 16) * 128 + kb + a_cb);
                ldsm_x4(ah[mi], Ah + swz(off));
            }
#pragma unroll
            for (int nb = 0; nb < 4; nb++) {
                uint32_t off = (uint32_t)((b_row + nb * 16) * 128 + kb + b_cb);
                ldsm_x4(bf[nb], Bh + swz(off));
            }
#pragma unroll
            for (int mi = 0; mi < 2; mi++)
#pragma unroll
                for (int ni = 0; ni < 8; ni++)
                    mma16816(acc[mi][ni], ah[mi], &bf[ni >> 1][(ni & 1) * 2]);
#pragma unroll
            for (int mi = 0; mi < 2; mi++) {
                uint32_t off = (uint32_t)((a_row + mi * 16) * 128 + kb + a_cb);
                ldsm_x4(al[mi], Al + swz(off));
            }
#pragma unroll
            for (int mi = 0; mi < 2; mi++)
#pragma unroll
                for (int ni = 0; ni < 8; ni++)
                    mma16816(acc[mi][ni], al[mi], &bf[ni >> 1][(ni & 1) * 2]);
#pragma unroll
            for (int nb = 0; nb < 4; nb++) {
                uint32_t off = (uint32_t)((b_row + nb * 16) * 128 + kb + b_cb);
                ldsm_x4(bf[nb], Bl + swz(off));
            }
#pragma unroll
            for (int mi = 0; mi < 2; mi++)
#pragma unroll
                for (int ni = 0; ni < 8; ni++)
                    mma16816(acc[mi][ni], ah[mi], &bf[ni >> 1][(ni & 1) * 2]);
        }

        // ---- produce A for chunk t+1 (overlaps tensor-pipe drain) ----
        if (t + 1 < NCH) produce_A(stgN, t + 1, m0, wid, lane);
    }

    // ---- epilogue: smem transpose to [o][m], coalesced stores ----
    __syncthreads();
    float* eb = (float*)smem;                 // 256 x 132 floats = 135KB (fits 192KB)
    const int er = lane >> 2;
    const int ec = (lane & 3) * 2;
#pragma unroll
    for (int mi = 0; mi < 2; mi++) {
#pragma unroll
        for (int ni = 0; ni < 8; ni++) {
            int m = wm + mi * 16 + er;
            int o = wn + ni * 8 + ec;
            eb[(o    ) * 132 + m    ] = acc[mi][ni][0];
            eb[(o + 1) * 132 + m    ] = acc[mi][ni][1];
            eb[(o    ) * 132 + m + 8] = acc[mi][ni][2];
            eb[(o + 1) * 132 + m + 8] = acc[mi][ni][3];
        }
    }
    __syncthreads();
    const int b   = m0 / HW;
    const int hw0 = m0 % HW;
#pragma unroll
    for (int i = 0; i < 16; i++) {
        int idx = tid + i * 512;
        int r = idx >> 5, c4 = (idx & 31) * 4;
        float4 v = *(const float4*)&eb[r * 132 + c4];
        *(float4*)&out[(size_t)(b * OC + r) * HW + hw0 + c4] = v;
    }
}

// ================= launch =================
extern "C" void kernel_launch(void* const* d_in, const int* in_sizes, int n_in,
                              void* d_out, int out_size)
{
    const float* x      = (const float*)d_in[0];
    const float* w_p    = (const float*)d_in[1];
    const float* b_p    = (const float*)d_in[2];
    const float* w_ad   = (const float*)d_in[3];
    const float* b_ad   = (const float*)d_in[4];
    const float* w_conv = (const float*)d_in[5];
    float* out = (float*)d_out;

    cudaFuncSetAttribute(mma_kernel, cudaFuncAttributeMaxDynamicSharedMemorySize, FUSE_SMEM);

    wq_kernel<<<OC, C>>>(w_conv);
    tr_kernel<<<dim3(HW / 32, C / 32, BDIM), 256>>>(x);
    offset_kernel<<<MPIX / 128, 256>>>(x, w_p, b_p, w_ad, b_ad);
    mma_kernel<<<MPIX / 128, 512, FUSE_SMEM>>>(out);
}